// round 4
// baseline (speedup 1.0000x reference)
#include <cuda_runtime.h>

// LocalCorrRatio: 1000 persistent-ish blocks; block p computes, for its patch,
// both shift variants (0 and 4) x both swap directions = 4 etas.
// Scalar inner loop (MUFU-bound by design), one wave at 8 CTAs/SM.

#define NPATCH 1000
#define W3 729
#define W3PAD 736        // 8 warps x 92 voxels
#define BINS 32
#define DIM 90
#define KEXP2 (-1386.4299343f)   // -961 * log2(e)

__device__ float g_eta[4 * NPATCH];
__device__ unsigned int g_count = 0;

__device__ __forceinline__ float ex2(float x) {
    float r; asm("ex2.approx.f32 %0, %1;" : "=f"(r) : "f"(x)); return r;
}

__global__ __launch_bounds__(256, 8) void lcr_kernel(const float* __restrict__ yt,
                                                     const float* __restrict__ yp,
                                                     float* __restrict__ out) {
    const int p = blockIdx.x;
    const int ph = p / 100;
    const int pw = (p / 10) % 10;
    const int pd = p % 10;

    __shared__ __align__(16) float ts[W3PAD];
    __shared__ __align__(16) float ps[W3PAD];
    __shared__ float accAw[8][BINS], accAx[8][BINS];
    __shared__ float accBw[8][BINS], accBx[8][BINS];
    __shared__ float red[4][8];
    __shared__ float s_meanT, s_varT, s_meanP, s_varP;
    __shared__ unsigned int s_islast;

    const int tid = threadIdx.x;
    const int warp = tid >> 5;
    const int lane = tid & 31;
    const float cb = (float)lane * (1.0f / 31.0f);

    for (int vp = 0; vp < 2; vp++) {
        const int shift = vp ? 4 : 0;

        // ---- Phase A: load patch + stats for both images ----
        if (tid < W3PAD - W3) { ts[W3 + tid] = 4.0f; ps[W3 + tid] = 4.0f; }  // w==0 pad

        float st = 0.0f, st2 = 0.0f, sp = 0.0f, sp2 = 0.0f;
        for (int idx = tid; idx < W3; idx += 256) {
            int i = idx / 81;
            int r = idx - i * 81;
            int j = r / 9;
            int k = r - j * 9;
            int gi = ph * 9 + i + shift; if (gi >= DIM) gi -= DIM;
            int gj = pw * 9 + j + shift; if (gj >= DIM) gj -= DIM;
            int gk = pd * 9 + k + shift; if (gk >= DIM) gk -= DIM;
            int g = (gi * DIM + gj) * DIM + gk;
            float tv = yt[g];
            float pv = yp[g];
            ts[idx] = tv;
            ps[idx] = pv;
            st += tv;  st2 = fmaf(tv, tv, st2);
            sp += pv;  sp2 = fmaf(pv, pv, sp2);
        }
        #pragma unroll
        for (int o = 16; o; o >>= 1) {
            st  += __shfl_xor_sync(0xffffffffu, st,  o);
            st2 += __shfl_xor_sync(0xffffffffu, st2, o);
            sp  += __shfl_xor_sync(0xffffffffu, sp,  o);
            sp2 += __shfl_xor_sync(0xffffffffu, sp2, o);
        }
        if (lane == 0) {
            red[0][warp] = st; red[1][warp] = st2;
            red[2][warp] = sp; red[3][warp] = sp2;
        }
        __syncthreads();
        if (tid == 0) {
            float a = 0, b = 0, c = 0, d = 0;
            #pragma unroll
            for (int w = 0; w < 8; w++) { a += red[0][w]; b += red[1][w]; c += red[2][w]; d += red[3][w]; }
            s_meanT = a * (1.0f / (float)W3);
            s_varT  = (b - a * a * (1.0f / (float)W3)) * (1.0f / (float)(W3 - 1));
            s_meanP = c * (1.0f / (float)W3);
            s_varP  = (d - c * c * (1.0f / (float)W3)) * (1.0f / (float)(W3 - 1));
        }
        __syncthreads();

        // ---- Phase B: lane = bin; warp w handles voxels [92w, 92w+92) ----
        const float2* t2 = (const float2*)ts;
        const float2* p2 = (const float2*)ps;
        const int base = warp * 46;

        // A: Y=pred, X=true.  B: Y=true, X=pred.  Two chains each.
        float SwA0 = 0.f, SwA1 = 0.f, SxA0 = 0.f, SxA1 = 0.f;
        float SwB0 = 0.f, SwB1 = 0.f, SxB0 = 0.f, SxB1 = 0.f;
        #pragma unroll 2
        for (int i = 0; i < 46; i++) {
            float2 tv = t2[base + i];
            float2 pv = p2[base + i];
            // voxel 0
            float dA0 = pv.x - cb;
            float dB0 = tv.x - cb;
            float wA0 = ex2(dA0 * (dA0 * KEXP2));
            float wB0 = ex2(dB0 * (dB0 * KEXP2));
            SwA0 += wA0;  SxA0 = fmaf(wA0, tv.x, SxA0);
            SwB0 += wB0;  SxB0 = fmaf(wB0, pv.x, SxB0);
            // voxel 1
            float dA1 = pv.y - cb;
            float dB1 = tv.y - cb;
            float wA1 = ex2(dA1 * (dA1 * KEXP2));
            float wB1 = ex2(dB1 * (dB1 * KEXP2));
            SwA1 += wA1;  SxA1 = fmaf(wA1, tv.y, SxA1);
            SwB1 += wB1;  SxB1 = fmaf(wB1, pv.y, SxB1);
        }
        accAw[warp][lane] = SwA0 + SwA1;
        accAx[warp][lane] = SxA0 + SxA1;
        accBw[warp][lane] = SwB0 + SwB1;
        accBx[warp][lane] = SxB0 + SxB1;
        __syncthreads();

        // ---- Phase C: warp 0 -> eta A, warp 1 -> eta B ----
        if (warp < 2) {
            float Sw = 0.0f, Sx = 0.0f;
            if (warp == 0) {
                #pragma unroll
                for (int w = 0; w < 8; w++) { Sw += accAw[w][lane]; Sx += accAx[w][lane]; }
            } else {
                #pragma unroll
                for (int w = 0; w < 8; w++) { Sw += accBw[w][lane]; Sx += accBx[w][lane]; }
            }
            float mean = (warp == 0) ? s_meanT : s_meanP;
            float var  = (warp == 0) ? s_varT  : s_varP;
            float mi = Sx / (Sw + 1e-5f);
            float dm = mi - mean;
            float num = Sw * dm * dm;
            float den = Sw;
            #pragma unroll
            for (int o = 16; o; o >>= 1) {
                num += __shfl_xor_sync(0xffffffffu, num, o);
                den += __shfl_xor_sync(0xffffffffu, den, o);
            }
            if (lane == 0) {
                g_eta[(vp * 2 + warp) * NPATCH + p] = (num / den) / (var + 1e-5f);
            }
        }
        __syncthreads();
    }

    // ---- Last block reduces all 4000 etas ----
    if (tid == 0) {
        __threadfence();
        unsigned int old = atomicAdd(&g_count, 1u);
        s_islast = (old == NPATCH - 1) ? 1u : 0u;
    }
    __syncthreads();
    if (s_islast) {
        __shared__ double sh[256];
        double s = 0.0;
        for (int i = tid; i < 4 * NPATCH; i += 256) s += (double)g_eta[i];
        sh[tid] = s;
        __syncthreads();
        #pragma unroll
        for (int o = 128; o; o >>= 1) {
            if (tid < o) sh[tid] += sh[tid + o];
            __syncthreads();
        }
        if (tid == 0) {
            out[0] = (float)(-sh[0] / 12000.0);
            g_count = 0;
        }
    }
}

extern "C" void kernel_launch(void* const* d_in, const int* in_sizes, int n_in,
                              void* d_out, int out_size) {
    const float* y_true = (const float*)d_in[0];
    const float* y_pred = (const float*)d_in[1];
    float* out = (float*)d_out;
    lcr_kernel<<<NPATCH, 256>>>(y_true, y_pred, out);
}

// round 5
// speedup vs baseline: 1.4642x; 1.4642x over previous
#include <cuda_runtime.h>

// LocalCorrRatio via shared-weight decomposition.
// Weights exp(-961(y-c)^2) are tiling-independent, so compute them ONCE per
// voxel x bin x image. Kernel 1: block = shift-0 patch; accumulates bin sums
// per sub-region (patch split at local coord 4 per axis -> 8 blocks of {4,5}^3),
// finalizes the 2 shift-0 etas, writes per-sub-region partials + stats to gmem.
// Kernel 2: each shift-4 patch = union of 8 sub-regions from 8 neighbor blocks;
// gathers partials, finalizes the 2 shifted etas, last block reduces all 4000.

#define NPATCH 1000
#define W3 729
#define DIM 90
#define KEXP2 (-1386.4299343f)   // -961 * log2(e)

__device__ float g_part[NPATCH * 8 * 4 * 32];   // [p][s][v][bin] v: SwA,SxA,SwB,SxB
__device__ float g_stats[NPATCH * 8 * 4];       // [p][s][{sumT,sumT2,sumP,sumP2}]
__device__ float g_eta[4 * NPATCH];
__device__ unsigned int g_count = 0;

__constant__ int cBASE[8]  = {0, 64, 144, 224, 324, 404, 504, 604};
__constant__ int cSPLIT[8] = {64, 144, 224, 324, 404, 504, 604, 729};

__device__ __forceinline__ float ex2(float x) {
    float r; asm("ex2.approx.f32 %0, %1;" : "=f"(r) : "f"(x)); return r;
}

__global__ __launch_bounds__(256) void lcr_part_kernel(const float* __restrict__ yt,
                                                       const float* __restrict__ yp) {
    const int p = blockIdx.x;
    const int ph = p / 100;
    const int pw = (p / 10) % 10;
    const int pd = p % 10;

    __shared__ float ts[W3];
    __shared__ float ps[W3];
    __shared__ float part_a[8][4][32];
    __shared__ float part_b[8][4][32];
    __shared__ float stats_sm[8][4];

    const int tid = threadIdx.x;
    const int warp = tid >> 5;
    const int lane = tid & 31;
    const float cb = (float)lane * (1.0f / 31.0f);

    // ---- Load patch into sub-region-major order ----
    for (int idx = tid; idx < W3; idx += 256) {
        int i = idx / 81;
        int r = idx - i * 81;
        int j = r / 9;
        int k = r - j * 9;
        int g = ((ph * 9 + i) * DIM + (pw * 9 + j)) * DIM + (pd * 9 + k);
        float tv = yt[g];
        float pv = yp[g];
        int sh = (i >= 4), sw_ = (j >= 4), sd_ = (k >= 4);
        int s = (sh << 2) | (sw_ << 1) | sd_;
        int ii = i - (sh ? 4 : 0);
        int jj = j - (sw_ ? 4 : 0);
        int kk = k - (sd_ ? 4 : 0);
        int nw = sw_ ? 5 : 4;
        int nd = sd_ ? 5 : 4;
        int dest = cBASE[s] + (ii * nw + jj) * nd + kk;
        ts[dest] = tv;
        ps[dest] = pv;
    }
    __syncthreads();

    // ---- Stats for sub-region s == warp (deterministic warp reduce) ----
    {
        int b0 = cBASE[warp];
        int b1 = (warp < 7) ? cBASE[warp + 1] : W3;
        float sT = 0.f, sT2 = 0.f, sP = 0.f, sP2 = 0.f;
        for (int idx = b0 + lane; idx < b1; idx += 32) {
            float tv = ts[idx], pv = ps[idx];
            sT += tv;  sT2 = fmaf(tv, tv, sT2);
            sP += pv;  sP2 = fmaf(pv, pv, sP2);
        }
        #pragma unroll
        for (int o = 16; o; o >>= 1) {
            sT  += __shfl_xor_sync(0xffffffffu, sT,  o);
            sT2 += __shfl_xor_sync(0xffffffffu, sT2, o);
            sP  += __shfl_xor_sync(0xffffffffu, sP,  o);
            sP2 += __shfl_xor_sync(0xffffffffu, sP2, o);
        }
        if (lane == 0) {
            stats_sm[warp][0] = sT;  stats_sm[warp][1] = sT2;
            stats_sm[warp][2] = sP;  stats_sm[warp][3] = sP2;
        }
    }

    // ---- Bin sums: lane = bin; warp's 92-voxel range split at one static
    //      sub-region boundary into 2 segments ----
    {
        const int s1b = 92 * warp;
        const int s1e = cSPLIT[warp];
        float SwA = 0.f, SxA = 0.f, SwB = 0.f, SxB = 0.f;
        #pragma unroll 4
        for (int idx = s1b; idx < s1e; idx++) {
            float tv = ts[idx], pv = ps[idx];
            float dA = pv - cb;
            float dB = tv - cb;
            float wA = ex2(dA * (dA * KEXP2));
            float wB = ex2(dB * (dB * KEXP2));
            SwA += wA;  SxA = fmaf(wA, tv, SxA);
            SwB += wB;  SxB = fmaf(wB, pv, SxB);
        }
        part_a[warp][0][lane] = SwA;
        part_a[warp][1][lane] = SxA;
        part_a[warp][2][lane] = SwB;
        part_a[warp][3][lane] = SxB;

        if (warp < 7) {
            const int s2b = s1e;
            const int s2e = 92 * warp + 92;
            SwA = 0.f; SxA = 0.f; SwB = 0.f; SxB = 0.f;
            #pragma unroll 4
            for (int idx = s2b; idx < s2e; idx++) {
                float tv = ts[idx], pv = ps[idx];
                float dA = pv - cb;
                float dB = tv - cb;
                float wA = ex2(dA * (dA * KEXP2));
                float wB = ex2(dB * (dB * KEXP2));
                SwA += wA;  SxA = fmaf(wA, tv, SxA);
                SwB += wB;  SxB = fmaf(wB, pv, SxB);
            }
            part_b[warp + 1][0][lane] = SwA;
            part_b[warp + 1][1][lane] = SxA;
            part_b[warp + 1][2][lane] = SwB;
            part_b[warp + 1][3][lane] = SxB;
        }
    }
    __syncthreads();

    // ---- Combine the two contributions per sub-region, publish to gmem ----
    {
        const int s = warp;
        float v0 = part_a[s][0][lane];
        float v1 = part_a[s][1][lane];
        float v2 = part_a[s][2][lane];
        float v3 = part_a[s][3][lane];
        if (s >= 1) {
            v0 += part_b[s][0][lane];
            v1 += part_b[s][1][lane];
            v2 += part_b[s][2][lane];
            v3 += part_b[s][3][lane];
        }
        part_a[s][0][lane] = v0;
        part_a[s][1][lane] = v1;
        part_a[s][2][lane] = v2;
        part_a[s][3][lane] = v3;
        int gb = ((p * 8 + s) * 4) * 32 + lane;
        g_part[gb]      = v0;
        g_part[gb + 32] = v1;
        g_part[gb + 64] = v2;
        g_part[gb + 96] = v3;
        if (lane < 4) g_stats[(p * 8 + s) * 4 + lane] = stats_sm[s][lane];
    }
    __syncthreads();

    // ---- Shift-0 etas (variants 0 and 1) ----
    if (warp < 2) {
        const int v0 = warp * 2;
        float Sw = 0.f, Sx = 0.f;
        #pragma unroll
        for (int s = 0; s < 8; s++) { Sw += part_a[s][v0][lane]; Sx += part_a[s][v0 + 1][lane]; }
        float sT = 0.f, sT2 = 0.f, sP = 0.f, sP2 = 0.f;
        #pragma unroll
        for (int s = 0; s < 8; s++) {
            sT += stats_sm[s][0]; sT2 += stats_sm[s][1];
            sP += stats_sm[s][2]; sP2 += stats_sm[s][3];
        }
        float sx  = (warp == 0) ? sT  : sP;    // X = true for dir A, pred for dir B
        float sx2 = (warp == 0) ? sT2 : sP2;
        float mean = sx * (1.0f / (float)W3);
        float var  = (sx2 - sx * sx * (1.0f / (float)W3)) * (1.0f / (float)(W3 - 1));
        float mi = Sx / (Sw + 1e-5f);
        float dm = mi - mean;
        float num = Sw * dm * dm;
        float den = Sw;
        #pragma unroll
        for (int o = 16; o; o >>= 1) {
            num += __shfl_xor_sync(0xffffffffu, num, o);
            den += __shfl_xor_sync(0xffffffffu, den, o);
        }
        if (lane == 0) g_eta[warp * NPATCH + p] = (num / den) / (var + 1e-5f);
    }
}

__global__ __launch_bounds__(64) void lcr_final_kernel(float* __restrict__ out) {
    const int p = blockIdx.x;
    const int a = p / 100;
    const int b = (p / 10) % 10;
    const int c = p % 10;
    const int tid = threadIdx.x;
    const int warp = tid >> 5;    // 0: dir A (variant 2), 1: dir B (variant 3)
    const int lane = tid & 31;

    __shared__ unsigned int s_islast;

    float Sw = 0.f, Sx = 0.f;
    float sT = 0.f, sT2 = 0.f, sP = 0.f, sP2 = 0.f;
    #pragma unroll
    for (int cc = 0; cc < 8; cc++) {
        int dh = (cc >> 2) & 1, dw = (cc >> 1) & 1, dd = cc & 1;
        int qa = a + dh; if (qa >= 10) qa -= 10;
        int qb = b + dw; if (qb >= 10) qb -= 10;
        int qc = c + dd; if (qc >= 10) qc -= 10;
        int q = (qa * 10 + qb) * 10 + qc;
        int s = 7 - cc;                 // delta=0 -> hi half, delta=1 -> lo half
        int gb = ((q * 8 + s) * 4 + warp * 2) * 32;
        Sw += g_part[gb + lane];
        Sx += g_part[gb + 32 + lane];
        int sb = (q * 8 + s) * 4;
        sT  += g_stats[sb + 0];
        sT2 += g_stats[sb + 1];
        sP  += g_stats[sb + 2];
        sP2 += g_stats[sb + 3];
    }
    float sx  = (warp == 0) ? sT  : sP;
    float sx2 = (warp == 0) ? sT2 : sP2;
    float mean = sx * (1.0f / (float)W3);
    float var  = (sx2 - sx * sx * (1.0f / (float)W3)) * (1.0f / (float)(W3 - 1));
    float mi = Sx / (Sw + 1e-5f);
    float dm = mi - mean;
    float num = Sw * dm * dm;
    float den = Sw;
    #pragma unroll
    for (int o = 16; o; o >>= 1) {
        num += __shfl_xor_sync(0xffffffffu, num, o);
        den += __shfl_xor_sync(0xffffffffu, den, o);
    }
    if (lane == 0) g_eta[(2 + warp) * NPATCH + p] = (num / den) / (var + 1e-5f);

    __threadfence();
    __syncthreads();
    if (tid == 0) {
        unsigned int old = atomicAdd(&g_count, 1u);
        s_islast = (old == NPATCH - 1) ? 1u : 0u;
    }
    __syncthreads();
    if (s_islast) {
        __threadfence();
        __shared__ double sh[64];
        double s = 0.0;
        for (int i = tid; i < 4 * NPATCH; i += 64) s += (double)g_eta[i];
        sh[tid] = s;
        __syncthreads();
        #pragma unroll
        for (int o = 32; o; o >>= 1) {
            if (tid < o) sh[tid] += sh[tid + o];
            __syncthreads();
        }
        if (tid == 0) {
            out[0] = (float)(-sh[0] / 12000.0);
            g_count = 0;
        }
    }
}

extern "C" void kernel_launch(void* const* d_in, const int* in_sizes, int n_in,
                              void* d_out, int out_size) {
    const float* y_true = (const float*)d_in[0];
    const float* y_pred = (const float*)d_in[1];
    float* out = (float*)d_out;
    lcr_part_kernel<<<NPATCH, 256>>>(y_true, y_pred);
    lcr_final_kernel<<<NPATCH, 64>>>(out);
}